// round 1
// baseline (speedup 1.0000x reference)
#include <cuda_runtime.h>
#include <cuda_bf16.h>

#define N_HALF 4096
#define TWO_N  8192
#define D      8
#define TILE   128
#define RPB    256           // rows per block (= threads per block)
#define CHUNK  256           // columns per block chunk
#define NCHUNK (TWO_N / CHUNK)   // 32

// Scratch (no allocations allowed; __device__ globals are the sanctioned path)
__device__ float g_z[TWO_N * D];
__device__ float g_raw[TWO_N];
__device__ float g_inv[TWO_N];                 // 1/(1 - clamp(raw, 0, 1-1e-5))
__device__ float g_denom[NCHUNK * TWO_N];      // partial denominators

__device__ __forceinline__ float fast_rcp(float x)  { float y; asm("rcp.approx.f32 %0, %1;"  : "=f"(y) : "f"(x)); return y; }
__device__ __forceinline__ float fast_sqrt(float x) { float y; asm("sqrt.approx.f32 %0, %1;" : "=f"(y) : "f"(x)); return y; }
__device__ __forceinline__ float fast_lg2(float x)  { float y; asm("lg2.approx.f32 %0, %1;"  : "=f"(y) : "f"(x)); return y; }
__device__ __forceinline__ float fast_ex2(float x)  { float y; asm("ex2.approx.f32 %0, %1;"  : "=f"(y) : "f"(x)); return y; }

#define LN2_F        0.6931471805599453f
#define TWO_LOG2E_F  2.8853900817779268f   // 2 * log2(e)
#define BOUNDARY_F   0.99999f              // 1 - 1e-5

// ---------------------------------------------------------------------------
// Kernel 1: concat + norms + clamped inverse factors
// ---------------------------------------------------------------------------
__global__ void prep_kernel(const float* __restrict__ zi,
                            const float* __restrict__ zj) {
    int i = blockIdx.x * blockDim.x + threadIdx.x;
    if (i >= TWO_N) return;
    const float* src = (i < N_HALF) ? (zi + (size_t)i * D)
                                    : (zj + (size_t)(i - N_HALF) * D);
    float4 a = *reinterpret_cast<const float4*>(src);
    float4 b = *reinterpret_cast<const float4*>(src + 4);
    *reinterpret_cast<float4*>(g_z + (size_t)i * D)     = a;
    *reinterpret_cast<float4*>(g_z + (size_t)i * D + 4) = b;
    float raw = a.x*a.x + a.y*a.y + a.z*a.z + a.w*a.w
              + b.x*b.x + b.y*b.y + b.z*b.z + b.w*b.w;
    float sqc = fminf(raw, BOUNDARY_F);        // raw >= 0 always
    g_raw[i] = raw;
    g_inv[i] = 1.0f / (1.0f - sqc);            // precise rcp is fine here (8192 ops)
}

// ---------------------------------------------------------------------------
// Kernel 2: pairwise similarity -> partial softmax denominators
// grid = (TWO_N/RPB, TWO_N/CHUNK), block = RPB
// ---------------------------------------------------------------------------
__global__ void __launch_bounds__(RPB)
pair_kernel() {
    __shared__ float4 sz[TILE * 2];   // [col*2 + half]
    __shared__ float  sraw[TILE];
    __shared__ float  sinv[TILE];

    const int i = blockIdx.x * RPB + threadIdx.x;

    const float4 za = *reinterpret_cast<const float4*>(g_z + (size_t)i * D);
    const float4 zb = *reinterpret_cast<const float4*>(g_z + (size_t)i * D + 4);
    const float raw_i  = g_raw[i];
    const float inv2_i = 2.0f * g_inv[i];

    float acc = 0.0f;
    const int j0 = blockIdx.y * CHUNK;

    for (int jt = j0; jt < j0 + CHUNK; jt += TILE) {
        __syncthreads();   // protect previous tile
        {
            int t = threadIdx.x;                       // 0..255
            sz[t] = *reinterpret_cast<const float4*>(
                        g_z + (size_t)(jt + (t >> 1)) * D + (t & 1) * 4);
            if (t < TILE) sraw[t]        = g_raw[jt + t];
            else          sinv[t - TILE] = g_inv[jt + t - TILE];
        }
        __syncthreads();

        #pragma unroll 4
        for (int jj = 0; jj < TILE; ++jj) {
            float4 ca = sz[jj * 2];
            float4 cb = sz[jj * 2 + 1];
            float dot = za.x * ca.x;
            dot = fmaf(za.y, ca.y, dot);
            dot = fmaf(za.z, ca.z, dot);
            dot = fmaf(za.w, ca.w, dot);
            dot = fmaf(zb.x, cb.x, dot);
            dot = fmaf(zb.y, cb.y, dot);
            dot = fmaf(zb.z, cb.z, dot);
            dot = fmaf(zb.w, cb.w, dot);

            float tsum = raw_i + sraw[jj];
            float sqd  = fmaxf(fmaf(-2.0f, dot, tsum), 0.0f);
            float x    = fmaf(sqd * inv2_i, sinv[jj], 1.0f);
            float x2   = fmaxf(fmaf(x, x, -1.0f), 0.0f);
            float s    = fast_sqrt(x2);                        // MUFU
            float l    = fast_lg2(x + s);                      // MUFU
            float den  = fmaf(l, LN2_F, 1.0f);                 // 1 + arcosh(x)
            float r    = fast_rcp(den);                        // MUFU (= sim)
            float e    = fast_ex2(TWO_LOG2E_F * r);            // MUFU (= exp(2*sim))
            if (jt + jj != i) acc += e;                        // exclude self
        }
    }
    g_denom[blockIdx.y * TWO_N + i] = acc;
}

// ---------------------------------------------------------------------------
// Kernel 3: combine partials, positives, final reduction
// 1 block, 1024 threads
// ---------------------------------------------------------------------------
__global__ void finalize_kernel(float* __restrict__ out) {
    __shared__ float red[1024];
    const int tid = threadIdx.x;
    float local = 0.0f;

    #pragma unroll
    for (int r = 0; r < TWO_N / 1024; ++r) {
        int i = tid + r * 1024;
        float denom = 0.0f;
        #pragma unroll
        for (int c = 0; c < NCHUNK; ++c)
            denom += g_denom[c * TWO_N + i];

        int p = (i < N_HALF) ? (i + N_HALF) : (i - N_HALF);
        float dot = 0.0f;
        #pragma unroll
        for (int d = 0; d < D; ++d)
            dot = fmaf(g_z[(size_t)i * D + d], g_z[(size_t)p * D + d], dot);

        float tsum = g_raw[i] + g_raw[p];
        float sqd  = fmaxf(fmaf(-2.0f, dot, tsum), 0.0f);
        float x    = fmaf(sqd * 2.0f * g_inv[i], g_inv[p], 1.0f);
        float x2   = fmaxf(fmaf(x, x, -1.0f), 0.0f);
        float dist = fast_lg2(x + fast_sqrt(x2)) * LN2_F;
        float sim  = 1.0f / (1.0f + dist);

        // loss_i = -(sim/T - log(denom)) = log(denom) - 2*sim
        local += fast_lg2(denom) * LN2_F - 2.0f * sim;
    }

    red[tid] = local;
    __syncthreads();
    #pragma unroll
    for (int s = 512; s > 0; s >>= 1) {
        if (tid < s) red[tid] += red[tid + s];
        __syncthreads();
    }
    if (tid == 0) out[0] = red[0] / (float)TWO_N;
}

// ---------------------------------------------------------------------------
extern "C" void kernel_launch(void* const* d_in, const int* in_sizes, int n_in,
                              void* d_out, int out_size) {
    const float* zi = (const float*)d_in[0];
    const float* zj = (const float*)d_in[1];
    float* out = (float*)d_out;

    prep_kernel<<<(TWO_N + 255) / 256, 256>>>(zi, zj);

    dim3 grid(TWO_N / RPB, TWO_N / CHUNK);   // (32, 32)
    pair_kernel<<<grid, RPB>>>();

    finalize_kernel<<<1, 1024>>>(out);
}

// round 2
// speedup vs baseline: 1.6965x; 1.6965x over previous
#include <cuda_runtime.h>
#include <cuda_bf16.h>

#define N_HALF 4096
#define TWO_N  8192
#define D      8
#define NT     16                 // number of 512-row tiles
#define RT     512                // rows per tile
#define BT     256                // threads per block (2 rows each)
#define CSPLIT 8                  // column octants per tile
#define CT     64                 // columns per block
#define NSLOT  (NT * CSPLIT)      // 128 partial slots per row
#define NPAIR  (NT * (NT + 1) / 2)   // 136 tile pairs
#define NBLK   (NPAIR * CSPLIT)      // 1088 blocks

// Scratch (__device__ globals; zero-initialized once at module load.
// Unused g_denom slots are never written and stay 0 across replays.)
__device__ float  g_z[TWO_N * D];
__device__ float2 g_ri[TWO_N];              // (raw sqnorm, 1/(1-clamped))
__device__ float  g_denom[NSLOT * TWO_N];   // 4 MB partial denominators
__device__ float  g_partial[32];

__device__ __forceinline__ float fast_rcp(float x)  { float y; asm("rcp.approx.f32 %0, %1;"  : "=f"(y) : "f"(x)); return y; }
__device__ __forceinline__ float fast_sqrt(float x) { float y; asm("sqrt.approx.f32 %0, %1;" : "=f"(y) : "f"(x)); return y; }
__device__ __forceinline__ float fast_lg2(float x)  { float y; asm("lg2.approx.f32 %0, %1;"  : "=f"(y) : "f"(x)); return y; }
__device__ __forceinline__ float fast_ex2(float x)  { float y; asm("ex2.approx.f32 %0, %1;"  : "=f"(y) : "f"(x)); return y; }

#define LN2_F        0.6931471805599453f
#define TWO_LOG2E_F  2.8853900817779268f   // 2 * log2(e)
#define BOUNDARY_F   0.99999f              // 1 - 1e-5

// Dot product with a FIXED fma ordering, shared by prep (self-norm) and pair
// kernels so the self-pair term cancels bit-exactly against E2 in finalize.
__device__ __forceinline__ float dot8(const float4& ua, const float4& ub,
                                      const float4& va, const float4& vb) {
    float d = ua.x * va.x;
    d = fmaf(ua.y, va.y, d);
    d = fmaf(ua.z, va.z, d);
    d = fmaf(ua.w, va.w, d);
    d = fmaf(ub.x, vb.x, d);
    d = fmaf(ub.y, vb.y, d);
    d = fmaf(ub.z, vb.z, d);
    d = fmaf(ub.w, vb.w, d);
    return d;
}

// exp(2 * poincare_sim) given dot and per-point factors
__device__ __forceinline__ float pair_e(float dot, float rawsum,
                                        float inv2i, float invj) {
    float sqd = fmaxf(fmaf(-2.0f, dot, rawsum), 0.0f);
    float x   = fmaf(sqd * inv2i, invj, 1.0f);
    float x2  = fmaxf(fmaf(x, x, -1.0f), 0.0f);
    float s   = fast_sqrt(x2);                 // MUFU
    float l   = fast_lg2(x + s);               // MUFU
    float den = fmaf(l, LN2_F, 1.0f);          // 1 + arcosh(x)
    float r   = fast_rcp(den);                 // MUFU (= sim)
    return fast_ex2(TWO_LOG2E_F * r);          // MUFU (= exp(2*sim))
}

// ---------------------------------------------------------------------------
// Kernel 1: concat + norms + clamped inverse factors
// ---------------------------------------------------------------------------
__global__ void prep_kernel(const float* __restrict__ zi,
                            const float* __restrict__ zj) {
    int i = blockIdx.x * blockDim.x + threadIdx.x;
    if (i >= TWO_N) return;
    const float* src = (i < N_HALF) ? (zi + (size_t)i * D)
                                    : (zj + (size_t)(i - N_HALF) * D);
    float4 a = *reinterpret_cast<const float4*>(src);
    float4 b = *reinterpret_cast<const float4*>(src + 4);
    *reinterpret_cast<float4*>(g_z + (size_t)i * D)     = a;
    *reinterpret_cast<float4*>(g_z + (size_t)i * D + 4) = b;
    float raw = dot8(a, b, a, b);              // same fma order as pair dot
    float sqc = fminf(raw, BOUNDARY_F);
    g_ri[i] = make_float2(raw, 1.0f / (1.0f - sqc));
}

// ---------------------------------------------------------------------------
// Kernel 2: symmetric pairwise tiles -> partial softmax denominators
// grid = NBLK (tile-pair x column-octant), block = 256 threads, 2 rows each
// ---------------------------------------------------------------------------
__global__ void __launch_bounds__(BT)
pair_kernel() {
    __shared__ float4 sz[CT * 2];      // column z data
    __shared__ float2 sri[CT];         // column (raw, inv)
    __shared__ float  wacc[8][CT];     // per-warp column accumulators

    const int t = threadIdx.x;
    const int w = t >> 5;

    // decode (a, b, h) from linear block index
    int p = blockIdx.x >> 3;
    int h = blockIdx.x & 7;
    int a = 0, rem = p;
    while (rem >= NT - a) { rem -= NT - a; ++a; }
    int b = a + rem;
    const bool diag = (a == b);

    const int jbase = b * RT + h * CT;

    // stage column tile
    if (t < CT * 2) {
        sz[t] = *reinterpret_cast<const float4*>(
                    g_z + (size_t)(jbase + (t >> 1)) * D + (size_t)(t & 1) * 4);
    } else if (t < CT * 3) {
        sri[t - CT * 2] = g_ri[jbase + (t - CT * 2)];
    }
    #pragma unroll
    for (int q = t; q < 8 * CT; q += BT) (&wacc[0][0])[q] = 0.0f;

    // two rows per thread
    const int i0 = a * RT + t;
    const int i1 = i0 + BT;
    const float4 za0 = *reinterpret_cast<const float4*>(g_z + (size_t)i0 * D);
    const float4 zb0 = *reinterpret_cast<const float4*>(g_z + (size_t)i0 * D + 4);
    const float4 za1 = *reinterpret_cast<const float4*>(g_z + (size_t)i1 * D);
    const float4 zb1 = *reinterpret_cast<const float4*>(g_z + (size_t)i1 * D + 4);
    const float2 ri0 = g_ri[i0];
    const float2 ri1 = g_ri[i1];
    const float raw0 = ri0.x, inv20 = 2.0f * ri0.y;
    const float raw1 = ri1.x, inv21 = 2.0f * ri1.y;

    __syncthreads();

    float acc0 = 0.0f, acc1 = 0.0f;

    if (diag) {
        #pragma unroll 4
        for (int k = 0; k < CT; ++k) {
            int jj = (t + k) & (CT - 1);
            float4 ca = sz[jj * 2];
            float4 cb = sz[jj * 2 + 1];
            float2 rj = sri[jj];
            float e0 = pair_e(dot8(za0, zb0, ca, cb), raw0 + rj.x, inv20, rj.y);
            float e1 = pair_e(dot8(za1, zb1, ca, cb), raw1 + rj.x, inv21, rj.y);
            acc0 += e0;
            acc1 += e1;
        }
    } else {
        volatile float* va = &wacc[w][0];
        #pragma unroll 2
        for (int k = 0; k < CT; ++k) {
            int jj = (t + k) & (CT - 1);   // distinct per lane within warp
            float4 ca = sz[jj * 2];
            float4 cb = sz[jj * 2 + 1];
            float2 rj = sri[jj];
            float e0 = pair_e(dot8(za0, zb0, ca, cb), raw0 + rj.x, inv20, rj.y);
            float e1 = pair_e(dot8(za1, zb1, ca, cb), raw1 + rj.x, inv21, rj.y);
            acc0 += e0;
            acc1 += e1;
            va[jj] = va[jj] + (e0 + e1);   // column-side accumulation
            __syncwarp();                  // order cross-lane RMW between k's
        }
    }

    // row-side slot: (tile b, octant h)
    const int rslot = b * CSPLIT + h;
    g_denom[(size_t)rslot * TWO_N + i0] = acc0;
    g_denom[(size_t)rslot * TWO_N + i1] = acc1;

    // column-side slot: (tile a, octant h) -- only for off-diagonal blocks
    if (!diag) {
        __syncthreads();
        if (t < CT) {
            float c = 0.0f;
            #pragma unroll
            for (int ww = 0; ww < 8; ++ww) c += wacc[ww][t];
            g_denom[(size_t)(a * CSPLIT + h) * TWO_N + jbase + t] = c;
        }
    }
}

// ---------------------------------------------------------------------------
// Kernel 3: per-row denom + positive-pair sim + block partial sums
// grid = 32, block = 256
// ---------------------------------------------------------------------------
__global__ void fin1_kernel() {
    __shared__ float red[256];
    const int tid = threadIdx.x;
    const int i = blockIdx.x * 256 + tid;

    float denom = 0.0f;
    #pragma unroll 8
    for (int c = 0; c < NSLOT; ++c)
        denom += g_denom[(size_t)c * TWO_N + i];
    denom -= fast_ex2(TWO_LOG2E_F);   // subtract self term (bit-exact cancel)

    const int p = (i < N_HALF) ? (i + N_HALF) : (i - N_HALF);
    float4 ua = *reinterpret_cast<const float4*>(g_z + (size_t)i * D);
    float4 ub = *reinterpret_cast<const float4*>(g_z + (size_t)i * D + 4);
    float4 va = *reinterpret_cast<const float4*>(g_z + (size_t)p * D);
    float4 vb = *reinterpret_cast<const float4*>(g_z + (size_t)p * D + 4);
    float2 ri = g_ri[i];
    float2 rj = g_ri[p];

    float dot = dot8(ua, ub, va, vb);
    float sqd = fmaxf(fmaf(-2.0f, dot, ri.x + rj.x), 0.0f);
    float x   = fmaf(sqd * 2.0f * ri.y, rj.y, 1.0f);
    float x2  = fmaxf(fmaf(x, x, -1.0f), 0.0f);
    float dist = fast_lg2(x + fast_sqrt(x2)) * LN2_F;
    float sim  = fast_rcp(1.0f + dist);

    red[tid] = fast_lg2(denom) * LN2_F - 2.0f * sim;
    __syncthreads();
    #pragma unroll
    for (int s = 128; s > 0; s >>= 1) {
        if (tid < s) red[tid] += red[tid + s];
        __syncthreads();
    }
    if (tid == 0) g_partial[blockIdx.x] = red[0];
}

// ---------------------------------------------------------------------------
// Kernel 4: final 32-way reduction
// ---------------------------------------------------------------------------
__global__ void fin2_kernel(float* __restrict__ out) {
    float v = g_partial[threadIdx.x];
    #pragma unroll
    for (int s = 16; s > 0; s >>= 1)
        v += __shfl_xor_sync(0xFFFFFFFFu, v, s);
    if (threadIdx.x == 0) out[0] = v / (float)TWO_N;
}

// ---------------------------------------------------------------------------
extern "C" void kernel_launch(void* const* d_in, const int* in_sizes, int n_in,
                              void* d_out, int out_size) {
    const float* zi = (const float*)d_in[0];
    const float* zj = (const float*)d_in[1];
    float* out = (float*)d_out;

    prep_kernel<<<(TWO_N + 255) / 256, 256>>>(zi, zj);
    pair_kernel<<<NBLK, BT>>>();
    fin1_kernel<<<32, 256>>>();
    fin2_kernel<<<1, 32>>>(out);
}

// round 3
// speedup vs baseline: 1.9782x; 1.1660x over previous
#include <cuda_runtime.h>

#define N_HALF 4096
#define TWO_N  8192
#define D      8
#define NT     16                    // row/col tiles of 512
#define RT     512
#define BT     128                   // threads per block
#define ROWS_PT 4                    // rows per thread (RT = 4*BT)
#define CSPLIT 8                     // column octants per tile
#define CT     64                    // columns per block
#define NSLOT  (NT * CSPLIT)         // 128 partial slots per row
#define NPAIR  (NT * (NT + 1) / 2)   // 136 tile pairs
#define NBLK   (NPAIR * CSPLIT)      // 1088 blocks

#define LN2_F        0.6931471805599453f
#define TWO_LOG2E_F  2.8853900817779268f
#define BOUNDARY_F   0.99999f

// __device__ scratch (allocation-free rule)
__device__ float        g_denom[NSLOT * TWO_N];   // 4 MB partials
__device__ float        g_partial[32];
__device__ unsigned int g_cnt;                     // zero-initialized

typedef unsigned long long u64;

__device__ __forceinline__ float fast_sqrt(float x) { float y; asm("sqrt.approx.f32 %0, %1;" : "=f"(y) : "f"(x)); return y; }
__device__ __forceinline__ float fast_lg2(float x)  { float y; asm("lg2.approx.f32 %0, %1;"  : "=f"(y) : "f"(x)); return y; }
__device__ __forceinline__ float fast_rcp(float x)  { float y; asm("rcp.approx.f32 %0, %1;"  : "=f"(y) : "f"(x)); return y; }
__device__ __forceinline__ float fast_ex2(float x)  { float y; asm("ex2.approx.f32 %0, %1;"  : "=f"(y) : "f"(x)); return y; }

__device__ __forceinline__ u64 pack2(float lo, float hi) {
    u64 r; asm("mov.b64 %0, {%1,%2};" : "=l"(r) : "f"(lo), "f"(hi)); return r;
}
__device__ __forceinline__ u64 mul2(u64 a, u64 b) {
    u64 r; asm("mul.rn.f32x2 %0, %1, %2;" : "=l"(r) : "l"(a), "l"(b)); return r;
}
__device__ __forceinline__ u64 fma2(u64 a, u64 b, u64 c) {
    u64 r; asm("fma.rn.f32x2 %0, %1, %2, %3;" : "=l"(r) : "l"(a), "l"(b), "l"(c)); return r;
}

// ---- shared building blocks (MUST be identical in pair + fin kernels so the
//      self-pair term cancels bit-exactly) -----------------------------------
__device__ __forceinline__ void load_point(const float* __restrict__ zi,
                                           const float* __restrict__ zj,
                                           int i, float4& a, float4& b) {
    const float* src = (i < N_HALF) ? (zi + (size_t)i * D)
                                    : (zj + (size_t)(i - N_HALF) * D);
    a = *reinterpret_cast<const float4*>(src);
    b = *reinterpret_cast<const float4*>(src + 4);
}

__device__ __forceinline__ float raw8(const float4& a, const float4& b) {
    float d = __fmul_rn(a.x, a.x);
    d = fmaf(a.y, a.y, d); d = fmaf(a.z, a.z, d); d = fmaf(a.w, a.w, d);
    d = fmaf(b.x, b.x, d); d = fmaf(b.y, b.y, d); d = fmaf(b.z, b.z, d);
    d = fmaf(b.w, b.w, d);
    return d;
}

// row-side augmented vector: a = [-4*inv*z(8); 2*inv*raw; 2*inv]
__device__ __forceinline__ void build_a(const float4& a, const float4& b, u64 A[5]) {
    float raw = raw8(a, b);
    float inv = 1.0f / (1.0f - fminf(raw, BOUNDARY_F));
    float m   = __fmul_rn(-4.0f, inv);
    A[0] = pack2(__fmul_rn(m, a.x), __fmul_rn(m, a.y));
    A[1] = pack2(__fmul_rn(m, a.z), __fmul_rn(m, a.w));
    A[2] = pack2(__fmul_rn(m, b.x), __fmul_rn(m, b.y));
    A[3] = pack2(__fmul_rn(m, b.z), __fmul_rn(m, b.w));
    float i2 = __fadd_rn(inv, inv);
    A[4] = pack2(__fmul_rn(i2, raw), i2);
}

// col-side augmented vector: b = [inv*z(8); inv; inv*raw]
__device__ __forceinline__ void build_b(const float4& a, const float4& b, u64 B[5]) {
    float raw = raw8(a, b);
    float inv = 1.0f / (1.0f - fminf(raw, BOUNDARY_F));
    B[0] = pack2(__fmul_rn(inv, a.x), __fmul_rn(inv, a.y));
    B[1] = pack2(__fmul_rn(inv, a.z), __fmul_rn(inv, a.w));
    B[2] = pack2(__fmul_rn(inv, b.x), __fmul_rn(inv, b.y));
    B[3] = pack2(__fmul_rn(inv, b.z), __fmul_rn(inv, b.w));
    B[4] = pack2(inv, __fmul_rn(inv, raw));
}

// x = max(a.b, 0) + 1    (clamp sqdist>=0 expressed as x>=1)
__device__ __forceinline__ float dot10_x(const u64 A[5], const u64 B[5]) {
    u64 s = mul2(A[4], B[4]);
    s = fma2(A[0], B[0], s);
    s = fma2(A[1], B[1], s);
    s = fma2(A[2], B[2], s);
    s = fma2(A[3], B[3], s);
    float lo, hi;
    asm("mov.b64 {%0,%1}, %2;" : "=f"(lo), "=f"(hi) : "l"(s));
    float t = fmaxf(__fadd_rn(lo, hi), 0.0f);
    return __fadd_rn(t, 1.0f);
}

// sim = 1/(1+arcosh(x));   e = exp(2*sim)
__device__ __forceinline__ float chain_sim(float x) {
    float x2 = fmaf(x, x, -1.0f);           // >= 0 since x >= 1
    float s  = fast_sqrt(x2);               // MUFU
    float l  = fast_lg2(__fadd_rn(x, s));   // MUFU
    float dn = fmaf(l, LN2_F, 1.0f);
    return fast_rcp(dn);                    // MUFU
}
__device__ __forceinline__ float chain_e(float x) {
    return fast_ex2(__fmul_rn(TWO_LOG2E_F, chain_sim(x)));   // MUFU
}

// ---------------------------------------------------------------------------
// Kernel 1: symmetric pairwise tiles -> partial softmax denominators
// grid = NBLK, block = BT (4 rows/thread), prep inlined
// ---------------------------------------------------------------------------
__global__ void __launch_bounds__(BT)
pair_kernel(const float* __restrict__ zi, const float* __restrict__ zj) {
    __shared__ u64   sb[5][CT];     // column augmented vectors (SoA)
    __shared__ float wacc[4][CT];   // per-warp column sums

    const int t    = threadIdx.x;
    const int lane = t & 31;
    const int w    = t >> 5;
    const int nxt  = (lane + 1) & 31;

    // decode (a, b, h)
    int p = blockIdx.x >> 3;
    int h = blockIdx.x & 7;
    int a = 0, rem = p;
    while (rem >= NT - a) { rem -= NT - a; ++a; }
    int b = a + rem;
    const bool diag = (a == b);
    const int jbase = b * RT + h * CT;

    // stage 64 columns
    if (t < CT) {
        float4 ca, cb;
        load_point(zi, zj, jbase + t, ca, cb);
        u64 B[5];
        build_b(ca, cb, B);
        sb[0][t] = B[0]; sb[1][t] = B[1]; sb[2][t] = B[2];
        sb[3][t] = B[3]; sb[4][t] = B[4];
    }

    // build 4 row vectors
    u64 A[ROWS_PT][5];
    #pragma unroll
    for (int r = 0; r < ROWS_PT; ++r) {
        float4 ra, rb;
        load_point(zi, zj, a * RT + r * BT + t, ra, rb);
        build_a(ra, rb, A[r]);
    }

    __syncthreads();

    float racc[ROWS_PT] = {0.f, 0.f, 0.f, 0.f};

    if (diag) {
        #pragma unroll 4
        for (int c = 0; c < CT; ++c) {                    // broadcast LDS
            u64 B[5] = { sb[0][c], sb[1][c], sb[2][c], sb[3][c], sb[4][c] };
            #pragma unroll
            for (int r = 0; r < ROWS_PT; ++r)
                racc[r] += chain_e(dot10_x(A[r], B));
        }
    } else {
        #pragma unroll
        for (int g = 0; g < 2; ++g) {
            float cacc = 0.0f;                            // systolic ring acc
            #pragma unroll 4
            for (int k = 0; k < 32; ++k) {
                int c = (g << 5) + ((lane + k) & 31);     // conflict-free
                u64 B[5] = { sb[0][c], sb[1][c], sb[2][c], sb[3][c], sb[4][c] };
                float e0 = chain_e(dot10_x(A[0], B));
                float e1 = chain_e(dot10_x(A[1], B));
                float e2 = chain_e(dot10_x(A[2], B));
                float e3 = chain_e(dot10_x(A[3], B));
                racc[0] += e0; racc[1] += e1; racc[2] += e2; racc[3] += e3;
                cacc += ((e0 + e1) + (e2 + e3));
                cacc = __shfl_sync(0xFFFFFFFFu, cacc, nxt, 32);
            }
            wacc[w][(g << 5) + lane] = cacc;              // lane holds col 'lane'
        }
    }

    // row-side partials: slot (b, h)
    const size_t rbase = (size_t)(b * CSPLIT + h) * TWO_N + a * RT + t;
    #pragma unroll
    for (int r = 0; r < ROWS_PT; ++r)
        g_denom[rbase + (size_t)r * BT] = racc[r];

    // column-side partials: slot (a, h)
    if (!diag) {
        __syncthreads();
        if (t < CT) {
            float c = ((wacc[0][t] + wacc[1][t]) + (wacc[2][t] + wacc[3][t]));
            g_denom[(size_t)(a * CSPLIT + h) * TWO_N + jbase + t] = c;
        }
    }
}

// ---------------------------------------------------------------------------
// Kernel 2: denom combine + self subtract + positives + full reduction
// grid = 32, block = 256; last block finishes via counter
// ---------------------------------------------------------------------------
__global__ void __launch_bounds__(256)
fin_kernel(const float* __restrict__ zi, const float* __restrict__ zj,
           float* __restrict__ out) {
    __shared__ float red[256];
    const int tid = threadIdx.x;
    const int i = blockIdx.x * 256 + tid;

    float denom = 0.0f;
    #pragma unroll 8
    for (int c = 0; c < NSLOT; ++c)
        denom += g_denom[(size_t)c * TWO_N + i];

    float4 ua, ub;
    load_point(zi, zj, i, ua, ub);
    u64 Ai[5], Bi[5];
    build_a(ua, ub, Ai);
    build_b(ua, ub, Bi);
    denom -= chain_e(dot10_x(Ai, Bi));        // bit-exact self-term cancel

    const int pp = (i < N_HALF) ? (i + N_HALF) : (i - N_HALF);
    float4 va, vb;
    load_point(zi, zj, pp, va, vb);
    u64 Bp[5];
    build_b(va, vb, Bp);
    float sim = chain_sim(dot10_x(Ai, Bp));

    red[tid] = fast_lg2(denom) * LN2_F - 2.0f * sim;
    __syncthreads();
    #pragma unroll
    for (int s = 128; s > 0; s >>= 1) {
        if (tid < s) red[tid] += red[tid + s];
        __syncthreads();
    }

    if (tid == 0) {
        g_partial[blockIdx.x] = red[0];
        __threadfence();
        unsigned tk = atomicAdd(&g_cnt, 1u);
        if (tk == 31u) {                       // last block finalizes
            __threadfence();
            float v = 0.0f;
            #pragma unroll
            for (int j = 0; j < 32; ++j) v += g_partial[j];
            out[0] = v / (float)TWO_N;
            g_cnt = 0;                         // reset for next graph replay
        }
    }
}

// ---------------------------------------------------------------------------
extern "C" void kernel_launch(void* const* d_in, const int* in_sizes, int n_in,
                              void* d_out, int out_size) {
    const float* zi = (const float*)d_in[0];
    const float* zj = (const float*)d_in[1];
    float* out = (float*)d_out;

    pair_kernel<<<NBLK, BT>>>(zi, zj);
    fin_kernel<<<32, 256>>>(zi, zj, out);
}

// round 4
// speedup vs baseline: 2.0559x; 1.0393x over previous
#include <cuda_runtime.h>

#define N_HALF 4096
#define TWO_N  8192
#define D      8
#define NT     16                    // row/col tiles of 512
#define RT     512
#define BT     128                   // threads per block
#define ROWS_PT 4                    // rows per thread (RT = 4*BT)
#define CSPLIT 4                     // column quarters per tile
#define CT     128                   // columns per block
#define NSLOT  (NT * CSPLIT)         // 64 partial slots per row
#define NPAIR  (NT * (NT + 1) / 2)   // 136 tile pairs
#define NBLK   (NPAIR * CSPLIT)      // 544 blocks -> single wave

#define LN2_F          0.6931471805599453f
#define HALF_LN2SQ_F   0.24022650695910072f   // ln2^2 / 2
#define HALF_LN2_F     0.34657359027997264f   // ln2 / 2
#define BOUNDARY_F     0.99999f

// __device__ scratch (allocation-free rule). Zero-initialized at module load;
// slots never written stay 0 forever (read-only zeros).
__device__ float        g_denom[NSLOT * TWO_N];   // 2 MB partials
__device__ float        g_partial[256];
__device__ unsigned int g_cnt;                     // zero-init

typedef unsigned long long u64;

__device__ __forceinline__ float fast_sqrt(float x) { float y; asm("sqrt.approx.f32 %0, %1;" : "=f"(y) : "f"(x)); return y; }
__device__ __forceinline__ float fast_lg2(float x)  { float y; asm("lg2.approx.f32 %0, %1;"  : "=f"(y) : "f"(x)); return y; }
__device__ __forceinline__ float fast_rcp(float x)  { float y; asm("rcp.approx.f32 %0, %1;"  : "=f"(y) : "f"(x)); return y; }
__device__ __forceinline__ float fast_ex2(float x)  { float y; asm("ex2.approx.f32 %0, %1;"  : "=f"(y) : "f"(x)); return y; }

__device__ __forceinline__ u64 pack2(float lo, float hi) {
    u64 r; asm("mov.b64 %0, {%1,%2};" : "=l"(r) : "f"(lo), "f"(hi)); return r;
}
__device__ __forceinline__ u64 fma2(u64 a, u64 b, u64 c) {
    u64 r; asm("fma.rn.f32x2 %0, %1, %2, %3;" : "=l"(r) : "l"(a), "l"(b), "l"(c)); return r;
}

// ---- shared building blocks (identical in both kernels: bit-exact self-term)
__device__ __forceinline__ void load_point(const float* __restrict__ zi,
                                           const float* __restrict__ zj,
                                           int i, float4& a, float4& b) {
    const float* src = (i < N_HALF) ? (zi + (size_t)i * D)
                                    : (zj + (size_t)(i - N_HALF) * D);
    a = *reinterpret_cast<const float4*>(src);
    b = *reinterpret_cast<const float4*>(src + 4);
}

__device__ __forceinline__ float raw8(const float4& a, const float4& b) {
    float d = __fmul_rn(a.x, a.x);
    d = fmaf(a.y, a.y, d); d = fmaf(a.z, a.z, d); d = fmaf(a.w, a.w, d);
    d = fmaf(b.x, b.x, d); d = fmaf(b.y, b.y, d); d = fmaf(b.z, b.z, d);
    d = fmaf(b.w, b.w, d);
    return d;
}

// row-side augmented vector: a = [-4*inv*z(8); 2*inv*raw; 2*inv]
__device__ __forceinline__ void build_a(const float4& a, const float4& b, u64 A[5]) {
    float raw = raw8(a, b);
    float inv = 1.0f / (1.0f - fminf(raw, BOUNDARY_F));
    float m   = __fmul_rn(-4.0f, inv);
    A[0] = pack2(__fmul_rn(m, a.x), __fmul_rn(m, a.y));
    A[1] = pack2(__fmul_rn(m, a.z), __fmul_rn(m, a.w));
    A[2] = pack2(__fmul_rn(m, b.x), __fmul_rn(m, b.y));
    A[3] = pack2(__fmul_rn(m, b.z), __fmul_rn(m, b.w));
    float i2 = __fadd_rn(inv, inv);
    A[4] = pack2(__fmul_rn(i2, raw), i2);
}

// col-side augmented vector: b = [inv*z(8); inv; inv*raw]
__device__ __forceinline__ void build_b(const float4& a, const float4& b, u64 B[5]) {
    float raw = raw8(a, b);
    float inv = 1.0f / (1.0f - fminf(raw, BOUNDARY_F));
    B[0] = pack2(__fmul_rn(inv, a.x), __fmul_rn(inv, a.y));
    B[1] = pack2(__fmul_rn(inv, a.z), __fmul_rn(inv, a.w));
    B[2] = pack2(__fmul_rn(inv, b.x), __fmul_rn(inv, b.y));
    B[3] = pack2(__fmul_rn(inv, b.z), __fmul_rn(inv, b.w));
    B[4] = pack2(inv, __fmul_rn(inv, raw));
}

// x = max(1 + a.b, 1)   (a.b = 2*inv_i*inv_j*sqdist >= 0 analytically)
__device__ __forceinline__ float dot10_x(const u64 A[5], const u64 B[5]) {
    u64 s = fma2(A[4], B[4], pack2(1.0f, 0.0f));   // fold +1 into the chain
    s = fma2(A[0], B[0], s);
    s = fma2(A[1], B[1], s);
    s = fma2(A[2], B[2], s);
    s = fma2(A[3], B[3], s);
    float lo, hi;
    asm("mov.b64 {%0,%1}, %2;" : "=f"(lo), "=f"(hi) : "l"(s));
    return fmaxf(__fadd_rn(lo, hi), 1.0f);
}

// e = exp(2*sim) = ex2( 1 / ((1 + arcosh(x)) * ln2/2) )
__device__ __forceinline__ float chain_e(float x) {
    float x2 = fmaf(x, x, -1.0f);                  // >= 0 since x >= 1
    float s  = fast_sqrt(x2);                      // MUFU
    float l  = fast_lg2(__fadd_rn(x, s));          // MUFU
    float dn = fmaf(l, HALF_LN2SQ_F, HALF_LN2_F);  // (1+dist)*ln2/2
    return fast_ex2(fast_rcp(dn));                 // MUFU, MUFU
}
// sim = 1/(1+arcosh(x))  (finalize only)
__device__ __forceinline__ float chain_sim(float x) {
    float x2 = fmaf(x, x, -1.0f);
    float s  = fast_sqrt(x2);
    float l  = fast_lg2(__fadd_rn(x, s));
    return fast_rcp(fmaf(l, LN2_F, 1.0f));
}

// ---------------------------------------------------------------------------
// Kernel 1: symmetric pairwise tiles -> partial softmax denominators
// grid = 544, block = 128 (4 rows/thread, 128 columns/block)
// ---------------------------------------------------------------------------
__global__ void __launch_bounds__(BT)
pair_kernel(const float* __restrict__ zi, const float* __restrict__ zj) {
    __shared__ u64   sb[5][CT];     // column augmented vectors (SoA)
    __shared__ float wacc[4][CT];   // per-warp column sums

    const int t    = threadIdx.x;
    const int lane = t & 31;
    const int w    = t >> 5;
    const int nxt  = (lane + 1) & 31;

    // decode (a, b, h)
    int p = blockIdx.x >> 2;
    int h = blockIdx.x & 3;
    int a = 0, rem = p;
    while (rem >= NT - a) { rem -= NT - a; ++a; }
    int b = a + rem;
    const bool diag = (a == b);
    const int jbase = b * RT + h * CT;

    // stage 128 columns (one per thread)
    {
        float4 ca, cb;
        load_point(zi, zj, jbase + t, ca, cb);
        u64 B[5];
        build_b(ca, cb, B);
        sb[0][t] = B[0]; sb[1][t] = B[1]; sb[2][t] = B[2];
        sb[3][t] = B[3]; sb[4][t] = B[4];
    }

    // build 4 row vectors
    u64 A[ROWS_PT][5];
    #pragma unroll
    for (int r = 0; r < ROWS_PT; ++r) {
        float4 ra, rb;
        load_point(zi, zj, a * RT + r * BT + t, ra, rb);
        build_a(ra, rb, A[r]);
    }

    __syncthreads();

    float racc[ROWS_PT] = {0.f, 0.f, 0.f, 0.f};

    if (diag) {
        #pragma unroll 4
        for (int c = 0; c < CT; ++c) {                    // broadcast LDS
            u64 B[5] = { sb[0][c], sb[1][c], sb[2][c], sb[3][c], sb[4][c] };
            #pragma unroll
            for (int r = 0; r < ROWS_PT; ++r)
                racc[r] += chain_e(dot10_x(A[r], B));
        }
    } else {
        #pragma unroll
        for (int g = 0; g < CT / 32; ++g) {
            float cacc = 0.0f;                            // systolic ring acc
            #pragma unroll 4
            for (int k = 0; k < 32; ++k) {
                int c = (g << 5) + ((lane + k) & 31);     // conflict-free
                u64 B[5] = { sb[0][c], sb[1][c], sb[2][c], sb[3][c], sb[4][c] };
                float e0 = chain_e(dot10_x(A[0], B));
                float e1 = chain_e(dot10_x(A[1], B));
                float e2 = chain_e(dot10_x(A[2], B));
                float e3 = chain_e(dot10_x(A[3], B));
                racc[0] += e0; racc[1] += e1; racc[2] += e2; racc[3] += e3;
                cacc += ((e0 + e1) + (e2 + e3));
                cacc = __shfl_sync(0xFFFFFFFFu, cacc, nxt, 32);
            }
            wacc[w][(g << 5) + lane] = cacc;              // lane holds col 'lane'
        }
    }

    // row-side partials: slot (b, h)
    const size_t rbase = (size_t)(b * CSPLIT + h) * TWO_N + a * RT + t;
    #pragma unroll
    for (int r = 0; r < ROWS_PT; ++r)
        g_denom[rbase + (size_t)r * BT] = racc[r];

    // column-side partials: slot (a, h)
    if (!diag) {
        __syncthreads();
        float c = ((wacc[0][t] + wacc[1][t]) + (wacc[2][t] + wacc[3][t]));
        g_denom[(size_t)(a * CSPLIT + h) * TWO_N + jbase + t] = c;
    }
}

// ---------------------------------------------------------------------------
// Kernel 2: denom combine (8 threads/row) + positives + full reduction
// grid = 256, block = 256 (32 rows per block)
// ---------------------------------------------------------------------------
__global__ void __launch_bounds__(256)
fin_kernel(const float* __restrict__ zi, const float* __restrict__ zj,
           float* __restrict__ out) {
    __shared__ float sacc[8][32];
    const int t = threadIdx.x;
    const int r = t & 31;          // row within block
    const int g = t >> 5;          // slot group (8 slots each)
    const int i = blockIdx.x * 32 + r;

    float d = 0.0f;
    #pragma unroll
    for (int c = 0; c < 8; ++c)
        d += g_denom[(size_t)(g * 8 + c) * TWO_N + i];
    sacc[g][r] = d;
    __syncthreads();

    if (g == 0) {                  // warp 0 finishes the 32 rows
        float denom = 0.0f;
        #pragma unroll
        for (int ww = 0; ww < 8; ++ww) denom += sacc[ww][r];

        float4 ua, ub;
        load_point(zi, zj, i, ua, ub);
        u64 Ai[5], Bi[5];
        build_a(ua, ub, Ai);
        build_b(ua, ub, Bi);
        denom -= chain_e(dot10_x(Ai, Bi));        // bit-exact self cancel

        const int pp = (i < N_HALF) ? (i + N_HALF) : (i - N_HALF);
        float4 va, vb;
        load_point(zi, zj, pp, va, vb);
        u64 Bp[5];
        build_b(va, vb, Bp);
        float sim = chain_sim(dot10_x(Ai, Bp));

        float loss = fast_lg2(denom) * LN2_F - 2.0f * sim;
        #pragma unroll
        for (int s = 16; s > 0; s >>= 1)
            loss += __shfl_xor_sync(0xFFFFFFFFu, loss, s);

        unsigned tk = 0u;
        if (r == 0) {
            g_partial[blockIdx.x] = loss;
            __threadfence();
            tk = atomicAdd(&g_cnt, 1u) + 1u;
        }
        tk = __shfl_sync(0xFFFFFFFFu, tk, 0);
        if (tk == 256u) {                          // last block finalizes
            __threadfence();
            float v = 0.0f;
            #pragma unroll
            for (int j = 0; j < 8; ++j) v += g_partial[r + j * 32];
            #pragma unroll
            for (int s = 16; s > 0; s >>= 1)
                v += __shfl_xor_sync(0xFFFFFFFFu, v, s);
            if (r == 0) {
                out[0] = v / (float)TWO_N;
                g_cnt = 0;                         // reset for next replay
            }
        }
    }
}

// ---------------------------------------------------------------------------
extern "C" void kernel_launch(void* const* d_in, const int* in_sizes, int n_in,
                              void* d_out, int out_size) {
    const float* zi = (const float*)d_in[0];
    const float* zj = (const float*)d_in[1];
    float* out = (float*)d_out;

    pair_kernel<<<NBLK, BT>>>(zi, zj);
    fin_kernel<<<256, 256>>>(zi, zj, out);
}